// round 16
// baseline (speedup 1.0000x reference)
#include <cuda_runtime.h>
#include <cuda_bf16.h>
#include <cuda_fp16.h>
#include <cuda_pipeline.h>
#include <mma.h>
#include <cstdint>

using namespace nvcuda;

#define NN 50000
#define HH 128
#define OUTC 64
#define DEPTH 3
#define LN_EPS 1e-5f
#define EGMAX 600000
#define ELMAX 400000
#define NB196 196
#define TILES 391          // ceil(NN/128)
#define LDT 40             // A smem leading dim (fp16): 80B rows, conflict-free LDSM
#define ATSZ (128 * LDT)   // 5120 elems per A tile

// ================= scratch =================
__device__ float g_x[NN * HH];
__device__ __half g_xh[NN * HH];
__device__ __half g_hG[NN * HH];
__device__ __half g_hL[NN * HH];
__device__ __half g_cat[NN * 2 * HH];
__device__ int   g_degG[NN];
__device__ int   g_degL[NN];
__device__ float g_dinvG[NN];
__device__ float g_dinvL[NN];
__device__ int   g_rowptrG[NN + 1];
__device__ int   g_rowptrL[NN + 1];
__device__ int   g_fillG[NN];
__device__ int   g_fillL[NN];
__device__ int2  g_edgeG[EGMAX];     // (col, coef bits)
__device__ int2  g_edgeL[ELMAX];
__device__ int   g_bsum[2][256];
// fp16 transposed weights [layer][N][K]
__device__ __half g_BG[DEPTH * HH * HH];
__device__ __half g_BL[DEPTH * HH * HH];
__device__ __half g_Blin[DEPTH * HH * 2 * HH];
__device__ __half g_Bfin[OUTC * HH];

// ================= setup kernels =================
__global__ void zero_deg_kernel(int* degG, int* degL, int n) {
    int i = blockIdx.x * blockDim.x + threadIdx.x;
    if (i < n) { degG[i] = 0; degL[i] = 0; }
}

__global__ void wsplit_all_kernel(const float* __restrict__ WG, const float* __restrict__ WLp,
                                  const float* __restrict__ linW, const float* __restrict__ finW,
                                  __half* BG, __half* BL, __half* Blin, __half* Bfin) {
    int seg = blockIdx.z;
    const float* W;
    __half* B;
    int K, N;
    if (seg < 3)      { K = HH;     N = HH;   W = WG  + (size_t)seg * HH * HH;           B = BG  + (size_t)seg * HH * HH; }
    else if (seg < 6) { K = HH;     N = HH;   W = WLp + (size_t)(seg - 3) * HH * HH;     B = BL  + (size_t)(seg - 3) * HH * HH; }
    else if (seg < 9) { K = 2 * HH; N = HH;   W = linW + (size_t)(seg - 6) * 2 * HH * HH; B = Blin + (size_t)(seg - 6) * 2 * HH * HH; }
    else              { K = HH;     N = OUTC; W = finW;                                   B = Bfin; }
    int n0 = blockIdx.x * 32, k0 = blockIdx.y * 32;
    if (n0 >= N || k0 >= K) return;
    __shared__ float t[32][33];
    int tx = threadIdx.x, ty = threadIdx.y;
    #pragma unroll
    for (int i = 0; i < 4; i++)
        t[ty + i * 8][tx] = W[(size_t)(k0 + ty + i * 8) * N + n0 + tx];
    __syncthreads();
    #pragma unroll
    for (int i = 0; i < 4; i++)
        B[(size_t)(n0 + ty + i * 8) * K + k0 + tx] = __float2half(t[tx][ty + i * 8]);
}

__global__ void init_split_kernel(const float4* __restrict__ xin4, float4* __restrict__ px4,
                                  __half* __restrict__ xh) {
    int i = blockIdx.x * blockDim.x + threadIdx.x;
    if (i >= NN * HH / 4) return;
    float4 v = xin4[i];
    px4[i] = v;
    __half2 a = __floats2half2_rn(v.x, v.y);
    __half2 b = __floats2half2_rn(v.z, v.w);
    uint2 u = { *(unsigned*)&a, *(unsigned*)&b };
    *reinterpret_cast<uint2*>(&xh[i * 4]) = u;
}

__global__ void count_deg_kernel(const int* __restrict__ dstG, int EG,
                                 const int* __restrict__ dstL, int EL,
                                 int* __restrict__ degG, int* __restrict__ degL) {
    int i = blockIdx.x * blockDim.x + threadIdx.x;
    if (i < EG) atomicAdd(&degG[dstG[i]], 1);
    else if (i < EG + EL) atomicAdd(&degL[dstL[i - EG]], 1);
}
__global__ void make_dinv_kernel(const int* __restrict__ degG, float* __restrict__ dinvG,
                                 const int* __restrict__ degL, float* __restrict__ dinvL, int n) {
    int i = blockIdx.x * blockDim.x + threadIdx.x;
    if (i < n) {
        dinvG[i] = rsqrtf((float)degG[i] + 2.0f);
        dinvL[i] = rsqrtf((float)degL[i] + 2.0f);
    }
}
__global__ void scan_block_kernel(const int* __restrict__ degG, const int* __restrict__ degL,
                                  int* __restrict__ rowG, int* __restrict__ rowL,
                                  int* __restrict__ bsum, int n) {
    __shared__ int s[256];
    const int* deg = blockIdx.y ? degL : degG;
    int* rowptr = blockIdx.y ? rowL : rowG;
    int* bs = bsum + blockIdx.y * 256;
    int i = blockIdx.x * 256 + threadIdx.x;
    int v = (i < n) ? deg[i] : 0;
    s[threadIdx.x] = v;
    __syncthreads();
    #pragma unroll
    for (int o = 1; o < 256; o <<= 1) {
        int t = (threadIdx.x >= o) ? s[threadIdx.x - o] : 0;
        __syncthreads();
        s[threadIdx.x] += t;
        __syncthreads();
    }
    if (i < n) rowptr[i] = s[threadIdx.x] - v;
    if (threadIdx.x == 255) bs[blockIdx.x] = s[255];
}
__global__ void scan_aux_kernel(int* bsum, int nb) {
    if (threadIdx.x == 0) {
        for (int y = 0; y < 2; y++) {
            int run = 0;
            int* b = bsum + y * 256;
            for (int i = 0; i < nb; i++) { int t = b[i]; b[i] = run; run += t; }
        }
    }
}
__global__ void scan_add_kernel(int* __restrict__ rowG, int* __restrict__ rowL,
                                int* __restrict__ fillG, int* __restrict__ fillL,
                                const int* __restrict__ bsum, int n, int EG, int EL) {
    int* rowptr = blockIdx.y ? rowL : rowG;
    int* fill = blockIdx.y ? fillL : fillG;
    const int* bs = bsum + blockIdx.y * 256;
    int E = blockIdx.y ? EL : EG;
    int i = blockIdx.x * 256 + threadIdx.x;
    if (i < n) {
        int v = rowptr[i] + bs[i >> 8];
        rowptr[i] = v;
        fill[i] = v;
    }
    if (i == 0) rowptr[n] = E;
}
__global__ void fill_csr_kernel(const int* __restrict__ Ge, int EG, const int* __restrict__ Le, int EL,
                                int* __restrict__ fillG, int* __restrict__ fillL,
                                int2* __restrict__ edgeG, int2* __restrict__ edgeL,
                                const float* __restrict__ dinvG, const float* __restrict__ dinvL) {
    int e = blockIdx.x * blockDim.x + threadIdx.x;
    const int* src; const int* dst; int* fill; int2* edge; const float* dinv; int E;
    if (blockIdx.y == 0) { src = Ge; dst = Ge + EG; fill = fillG; edge = edgeG; dinv = dinvG; E = EG; }
    else                 { src = Le; dst = Le + EL; fill = fillL; edge = edgeL; dinv = dinvL; E = EL; }
    if (e < E) {
        int s = src[e], d = dst[e];
        int p = atomicAdd(&fill[d], 1);
        float c = dinv[s] * dinv[d];
        edge[p] = make_int2(s, __float_as_int(c));
    }
}

// ===== dual-branch GEMM K=128 NOUT=128: 4 warps, 64x64 warp tiles, B resident, fp16 out ====
__global__ __launch_bounds__(128, 2)
void gemm_dual64_kernel(const __half* __restrict__ A,
                        const __half* __restrict__ B0, const __half* __restrict__ B1,
                        __half* __restrict__ Ch0, __half* __restrict__ Ch1, int M) {
    constexpr int K = 128;
    constexpr int LDB = 136;
    constexpr int BTILE = 128 * LDB;
    extern __shared__ __half sm[];
    __half* Bs = sm;
    __half* Astg = sm + BTILE;

    const __half* gB = blockIdx.y ? B1 : B0;
    __half* Ch = blockIdx.y ? Ch1 : Ch0;

    const int tid = threadIdx.x;
    const int wid = tid >> 5;
    const int lane = tid & 31;
    const int wr = wid >> 1;
    const int wc = wid & 1;
    const int row0 = blockIdx.x * 128;

    wmma::fragment<wmma::accumulator, 16, 16, 16, float> acc[4][4];
    #pragma unroll
    for (int i = 0; i < 4; i++)
        #pragma unroll
        for (int j = 0; j < 4; j++)
            wmma::fill_fragment(acc[i][j], 0.0f);

    auto load_A = [&](int s, int kc) {
        __half* base = Astg + s * ATSZ;
        #pragma unroll
        for (int c = tid; c < 512; c += 128) {
            int r = c >> 2;
            int ko = (c & 3) * 8;
            int gr = row0 + r;
            if (gr < M)
                __pipeline_memcpy_async(&base[r * LDT + ko], &A[(size_t)gr * K + kc * 32 + ko], 16);
        }
    };

    #pragma unroll
    for (int c = tid; c < 128 * 16; c += 128) {
        int r = c >> 4;
        int ko = (c & 15) * 8;
        __pipeline_memcpy_async(&Bs[r * LDB + ko], &gB[(size_t)r * K + ko], 16);
    }
    load_A(0, 0);
    __pipeline_commit();

    #pragma unroll
    for (int kc = 0; kc < 4; kc++) {
        if (kc + 1 < 4) {
            load_A((kc + 1) & 1, kc + 1);
            __pipeline_commit();
            __pipeline_wait_prior(1);
        } else {
            __pipeline_wait_prior(0);
        }
        __syncthreads();

        __half* Ahs = Astg + (kc & 1) * ATSZ;

        #pragma unroll
        for (int ks = 0; ks < 32; ks += 16) {
            int kcol = kc * 32 + ks;
            wmma::fragment<wmma::matrix_a, 16, 16, 16, __half, wmma::row_major> fa[4];
            #pragma unroll
            for (int i = 0; i < 4; i++)
                wmma::load_matrix_sync(fa[i], &Ahs[(wr * 64 + i * 16) * LDT + ks], LDT);
            wmma::fragment<wmma::matrix_b, 16, 16, 16, __half, wmma::col_major> fb[4];
            #pragma unroll
            for (int j = 0; j < 4; j++)
                wmma::load_matrix_sync(fb[j], &Bs[(wc * 64 + j * 16) * LDB + kcol], LDB);
            #pragma unroll
            for (int i = 0; i < 4; i++)
                #pragma unroll
                for (int j = 0; j < 4; j++)
                    wmma::mma_sync(acc[i][j], fa[i], fb[j], acc[i][j]);
        }
        __syncthreads();
    }

    float* st = reinterpret_cast<float*>(sm) + wid * 320;
    #pragma unroll
    for (int i = 0; i < 4; i++)
        #pragma unroll
        for (int j = 0; j < 4; j++) {
            wmma::store_matrix_sync(st, acc[i][j], 20, wmma::mem_row_major);
            __syncwarp();
            #pragma unroll
            for (int e = 0; e < 8; e++) {
                int idx = lane + e * 32;
                int r = idx >> 4;
                int c = idx & 15;
                int grow = row0 + wr * 64 + i * 16 + r;
                int gcol = wc * 64 + j * 16 + c;
                if (grow < M)
                    Ch[(size_t)grow * 128 + gcol] = __float2half(st[r * 20 + c]);
            }
            __syncwarp();
        }
}

// ================= fp16 GEMM, B resident, A double-buffered (8 warps, 32xHALFN tiles) =======
template <int NOUT, int KK>
__global__ __launch_bounds__(256, 2)
void gemm_bres_kernel(const __half* __restrict__ A, int lda,
                      const __half* __restrict__ B0, const __half* __restrict__ B1,
                      float* __restrict__ C0, float* __restrict__ C1, int ldc,
                      __half* __restrict__ Ch0, __half* __restrict__ Ch1,
                      const float* __restrict__ bias0, const float* __restrict__ bias1,
                      int M) {
    constexpr int HALFN = NOUT / 2;
    constexpr int NF = HALFN / 16;
    constexpr int LDB = KK + 8;
    constexpr int BTILE = NOUT * LDB;
    constexpr int NC = KK / 32;
    extern __shared__ __half sm[];
    __half* Bs = sm;
    __half* Astg = sm + BTILE;

    const __half* gB = blockIdx.y ? B1 : B0;
    float* C = blockIdx.y ? C1 : C0;
    __half* Ch = blockIdx.y ? Ch1 : Ch0;
    const float* bias = blockIdx.y ? bias1 : bias0;

    const int tid = threadIdx.x;
    const int wid = tid >> 5;
    const int lane = tid & 31;
    const int wr = wid >> 1;
    const int wc = wid & 1;
    const int row0 = blockIdx.x * 128;

    wmma::fragment<wmma::accumulator, 16, 16, 16, float> acc[2][NF];
    #pragma unroll
    for (int i = 0; i < 2; i++)
        #pragma unroll
        for (int j = 0; j < NF; j++)
            wmma::fill_fragment(acc[i][j], 0.0f);

    auto load_A = [&](int s, int kc) {
        __half* base = Astg + s * ATSZ;
        #pragma unroll
        for (int c = tid; c < 512; c += 256) {
            int r = c >> 2;
            int ko = (c & 3) * 8;
            int gr = row0 + r;
            if (gr < M)
                __pipeline_memcpy_async(&base[r * LDT + ko], &A[(size_t)gr * lda + kc * 32 + ko], 16);
        }
    };

    #pragma unroll
    for (int c = tid; c < NOUT * (KK / 8); c += 256) {
        int r = c / (KK / 8);
        int ko = (c % (KK / 8)) * 8;
        __pipeline_memcpy_async(&Bs[r * LDB + ko], &gB[(size_t)r * KK + ko], 16);
    }
    load_A(0, 0);
    __pipeline_commit();

    #pragma unroll
    for (int kc = 0; kc < NC; kc++) {
        if (kc + 1 < NC) {
            load_A((kc + 1) & 1, kc + 1);
            __pipeline_commit();
            __pipeline_wait_prior(1);
        } else {
            __pipeline_wait_prior(0);
        }
        __syncthreads();

        __half* Ahs = Astg + (kc & 1) * ATSZ;

        #pragma unroll
        for (int ks = 0; ks < 32; ks += 16) {
            int kcol = kc * 32 + ks;
            wmma::fragment<wmma::matrix_a, 16, 16, 16, __half, wmma::row_major> fa[2];
            #pragma unroll
            for (int i = 0; i < 2; i++)
                wmma::load_matrix_sync(fa[i], &Ahs[(wr * 32 + i * 16) * LDT + ks], LDT);
            wmma::fragment<wmma::matrix_b, 16, 16, 16, __half, wmma::col_major> fb[NF];
            #pragma unroll
            for (int j = 0; j < NF; j++)
                wmma::load_matrix_sync(fb[j], &Bs[(wc * HALFN + j * 16) * LDB + kcol], LDB);
            #pragma unroll
            for (int i = 0; i < 2; i++)
                #pragma unroll
                for (int j = 0; j < NF; j++)
                    wmma::mma_sync(acc[i][j], fa[i], fb[j], acc[i][j]);
        }
        __syncthreads();
    }

    float* st = reinterpret_cast<float*>(sm) + wid * 320;
    #pragma unroll
    for (int i = 0; i < 2; i++)
        #pragma unroll
        for (int j = 0; j < NF; j++) {
            wmma::store_matrix_sync(st, acc[i][j], 20, wmma::mem_row_major);
            __syncwarp();
            #pragma unroll
            for (int e = 0; e < 8; e++) {
                int idx = lane + e * 32;
                int r = idx >> 4;
                int c = idx & 15;
                int grow = row0 + wr * 32 + i * 16 + r;
                int gcol = wc * HALFN + j * 16 + c;
                if (grow < M) {
                    float v = st[r * 20 + c];
                    if (bias) v += __ldg(&bias[gcol]);
                    if (C)  C[(size_t)grow * ldc + gcol] = v;
                    if (Ch) Ch[(size_t)grow * ldc + gcol] = __float2half(v);
                }
            }
            __syncwarp();
        }
}

// ===== fused gather: software-pipelined edge descriptors (prefetch next 8 while rows load) ==
__global__ void gather_ln_kernel(const uint2* __restrict__ hG8, const uint2* __restrict__ hL8,
                                 const float4* __restrict__ x4,
                                 const int* __restrict__ rowG, const int* __restrict__ rowL,
                                 const int2* __restrict__ edgeG, const int2* __restrict__ edgeL,
                                 const float* __restrict__ dinvG, const float* __restrict__ dinvL,
                                 const float4* __restrict__ biasG4, const float4* __restrict__ biasL4,
                                 const float4* __restrict__ g4, const float4* __restrict__ b4,
                                 __half* __restrict__ cat, int residual) {
    int warp = (blockIdx.x * blockDim.x + threadIdx.x) >> 5;
    int lane = threadIdx.x & 31;
    if (warp >= NN) return;
    int n = warp;
    int half = blockIdx.y;

    const uint2* h8 = half ? hL8 : hG8;
    const int* rowptr = half ? rowL : rowG;
    const int2* edge = half ? edgeL : edgeG;
    const float* dinv = half ? dinvL : dinvG;
    const float4* bias4 = half ? biasL4 : biasG4;

    auto h2f4 = [](uint2 u) -> float4 {
        __half2 a = *reinterpret_cast<__half2*>(&u.x);
        __half2 b = *reinterpret_cast<__half2*>(&u.y);
        float2 fa = __half22float2(a);
        float2 fb = __half22float2(b);
        return make_float4(fa.x, fa.y, fb.x, fb.y);
    };

    float dv = __ldg(&dinv[n]);
    float sl = 2.0f * dv * dv;
    float4 h = h2f4(h8[n * 32 + lane]);
    float4 bb = __ldg(&bias4[lane]);
    float4 acc;
    acc.x = h.x * sl + bb.x;
    acc.y = h.y * sl + bb.y;
    acc.z = h.z * sl + bb.z;
    acc.w = h.w * sl + bb.w;

    int e = __ldg(&rowptr[n]);
    int e1 = __ldg(&rowptr[n + 1]);

    // software-pipelined 8-wide main loop
    int2 p[8];
    bool have = (e + 7 < e1);
    if (have) {
        #pragma unroll
        for (int q = 0; q < 8; q++) p[q] = __ldg(&edge[e + q]);
    }
    while (have) {
        int en = e + 8;
        bool haveNext = (en + 7 < e1);
        // issue row loads for current batch
        uint2 u[8];
        #pragma unroll
        for (int q = 0; q < 8; q++) u[q] = h8[p[q].x * 32 + lane];
        // prefetch next batch of descriptors (overlaps with row loads in flight)
        int2 pn[8];
        if (haveNext) {
            #pragma unroll
            for (int q = 0; q < 8; q++) pn[q] = __ldg(&edge[en + q]);
        }
        #pragma unroll
        for (int q = 0; q < 8; q++) {
            float c = __int_as_float(p[q].y);
            float4 v = h2f4(u[q]);
            acc.x += c * v.x;
            acc.y += c * v.y;
            acc.z += c * v.z;
            acc.w += c * v.w;
        }
        #pragma unroll
        for (int q = 0; q < 8; q++) p[q] = pn[q];
        e = en;
        have = haveNext;
    }
    if (e + 3 < e1) {
        int2 pt[4];
        #pragma unroll
        for (int q = 0; q < 4; q++) pt[q] = __ldg(&edge[e + q]);
        uint2 u[4];
        #pragma unroll
        for (int q = 0; q < 4; q++) u[q] = h8[pt[q].x * 32 + lane];
        #pragma unroll
        for (int q = 0; q < 4; q++) {
            float c = __int_as_float(pt[q].y);
            float4 v = h2f4(u[q]);
            acc.x += c * v.x;
            acc.y += c * v.y;
            acc.z += c * v.z;
            acc.w += c * v.w;
        }
        e += 4;
    }
    for (; e < e1; e++) {
        int2 p0 = __ldg(&edge[e]);
        float c0 = __int_as_float(p0.y);
        float4 v0 = h2f4(h8[p0.x * 32 + lane]);
        acc.x += c0 * v0.x; acc.y += c0 * v0.y; acc.z += c0 * v0.z; acc.w += c0 * v0.w;
    }

    float s1 = acc.x + acc.y + acc.z + acc.w;
    float s2 = acc.x * acc.x + acc.y * acc.y + acc.z * acc.z + acc.w * acc.w;
    #pragma unroll
    for (int o = 16; o > 0; o >>= 1) {
        s1 += __shfl_xor_sync(0xffffffffu, s1, o);
        s2 += __shfl_xor_sync(0xffffffffu, s2, o);
    }
    float mu = s1 * (1.0f / HH);
    float var = s2 * (1.0f / HH) - mu * mu;
    float rstd = rsqrtf(var + LN_EPS);

    float4 gg = __ldg(&g4[lane]);
    float4 be = __ldg(&b4[lane]);
    float4 y;
    y.x = fmaxf((acc.x - mu) * rstd * gg.x + be.x, 0.0f);
    y.y = fmaxf((acc.y - mu) * rstd * gg.y + be.y, 0.0f);
    y.z = fmaxf((acc.z - mu) * rstd * gg.z + be.z, 0.0f);
    y.w = fmaxf((acc.w - mu) * rstd * gg.w + be.w, 0.0f);
    if (residual) {
        float4 xv = x4[n * 32 + lane];
        y.x += xv.x; y.y += xv.y; y.z += xv.z; y.w += xv.w;
    }
    __half2 ya = __floats2half2_rn(y.x, y.y);
    __half2 yb = __floats2half2_rn(y.z, y.w);
    uint2 u = { *(unsigned*)&ya, *(unsigned*)&yb };
    *reinterpret_cast<uint2*>(&cat[(size_t)n * 256 + half * 128 + lane * 4]) = u;
}

// ================= launch =================
extern "C" void kernel_launch(void* const* d_in, const int* in_sizes, int n_in,
                              void* d_out, int out_size) {
    const float* x_in  = (const float*)d_in[0];
    const float* WL    = (const float*)d_in[1];
    const float* bL    = (const float*)d_in[2];
    const float* WG    = (const float*)d_in[3];
    const float* bG    = (const float*)d_in[4];
    const float* linW  = (const float*)d_in[5];
    const float* linb  = (const float*)d_in[6];
    const float* ln_g  = (const float*)d_in[7];
    const float* ln_b  = (const float*)d_in[8];
    const float* finW  = (const float*)d_in[9];
    const float* finb  = (const float*)d_in[10];
    const int*   Ge    = (const int*)d_in[11];
    const int*   Le    = (const int*)d_in[12];
    int E_G = in_sizes[11] / 2;
    int E_L = in_sizes[12] / 2;
    float* out = (float*)d_out;

    float *px, *pdinvG, *pdinvL;
    __half *pxh, *phG, *phL, *pcat;
    int *pdegG, *pdegL, *prowG, *prowL, *pfillG, *pfillL, *pbsum;
    int2 *pedgeG, *pedgeL;
    __half *pBG, *pBL, *pBlin, *pBfin;
    cudaGetSymbolAddress((void**)&px,     g_x);
    cudaGetSymbolAddress((void**)&pxh,    g_xh);
    cudaGetSymbolAddress((void**)&phG,    g_hG);
    cudaGetSymbolAddress((void**)&phL,    g_hL);
    cudaGetSymbolAddress((void**)&pcat,   g_cat);
    cudaGetSymbolAddress((void**)&pdegG,  g_degG);
    cudaGetSymbolAddress((void**)&pdegL,  g_degL);
    cudaGetSymbolAddress((void**)&pdinvG, g_dinvG);
    cudaGetSymbolAddress((void**)&pdinvL, g_dinvL);
    cudaGetSymbolAddress((void**)&prowG,  g_rowptrG);
    cudaGetSymbolAddress((void**)&prowL,  g_rowptrL);
    cudaGetSymbolAddress((void**)&pfillG, g_fillG);
    cudaGetSymbolAddress((void**)&pfillL, g_fillL);
    cudaGetSymbolAddress((void**)&pedgeG, g_edgeG);
    cudaGetSymbolAddress((void**)&pedgeL, g_edgeL);
    cudaGetSymbolAddress((void**)&pbsum,  g_bsum);
    cudaGetSymbolAddress((void**)&pBG,    g_BG);
    cudaGetSymbolAddress((void**)&pBL,    g_BL);
    cudaGetSymbolAddress((void**)&pBlin,  g_Blin);
    cudaGetSymbolAddress((void**)&pBfin,  g_Bfin);

    const int SM_DUAL   = (128 * 136 + 2 * ATSZ) * 2;    // 55296
    const int SM_CONCAT = (64 * 264 + 2 * ATSZ) * 2;     // 54272
    const int SM_FINAL  = (64 * 136 + 2 * ATSZ) * 2;     // 37888

    static cudaStream_t s1 = nullptr;
    static cudaEvent_t evFork1, evJoin1;
    static int attr_set = 0;
    if (!attr_set) {
        cudaFuncSetAttribute((const void*)gemm_dual64_kernel, cudaFuncAttributeMaxDynamicSharedMemorySize, SM_DUAL);
        cudaFuncSetAttribute((const void*)gemm_bres_kernel<64, 256>, cudaFuncAttributeMaxDynamicSharedMemorySize, SM_CONCAT);
        cudaFuncSetAttribute((const void*)gemm_bres_kernel<64, 128>, cudaFuncAttributeMaxDynamicSharedMemorySize, SM_FINAL);
        cudaStreamCreateWithFlags(&s1, cudaStreamNonBlocking);
        cudaEventCreateWithFlags(&evFork1, cudaEventDisableTiming);
        cudaEventCreateWithFlags(&evJoin1, cudaEventDisableTiming);
        attr_set = 1;
    }

    // ---- fork: CSR build on side stream ----
    cudaEventRecord(evFork1, 0);
    cudaStreamWaitEvent(s1, evFork1, 0);

    zero_deg_kernel<<<NB196, 256, 0, s1>>>(pdegG, pdegL, NN);
    count_deg_kernel<<<(E_G + E_L + 255) / 256, 256, 0, s1>>>(Ge + E_G, E_G, Le + E_L, E_L, pdegG, pdegL);
    make_dinv_kernel<<<NB196, 256, 0, s1>>>(pdegG, pdinvG, pdegL, pdinvL, NN);
    scan_block_kernel<<<dim3(NB196, 2), 256, 0, s1>>>(pdegG, pdegL, prowG, prowL, pbsum, NN);
    scan_aux_kernel<<<1, 32, 0, s1>>>(pbsum, NB196);
    scan_add_kernel<<<dim3(NB196, 2), 256, 0, s1>>>(prowG, prowL, pfillG, pfillL, pbsum, NN, E_G, E_L);
    int fe = (E_G > E_L ? E_G : E_L);
    fill_csr_kernel<<<dim3((fe + 255) / 256, 2), 256, 0, s1>>>(Ge, E_G, Le, E_L,
        pfillG, pfillL, pedgeG, pedgeL, pdinvG, pdinvL);
    cudaEventRecord(evJoin1, s1);

    wsplit_all_kernel<<<dim3(4, 8, 10), dim3(32, 8)>>>(WG, WL, linW, finW, pBG, pBL, pBlin, pBfin);
    init_split_kernel<<<(NN * HH / 4 + 255) / 256, 256>>>((const float4*)x_in, (float4*)px, pxh);
    gemm_dual64_kernel<<<dim3(TILES, 2), 128, SM_DUAL>>>(pxh, pBG, pBL, phG, phL, NN);

    cudaStreamWaitEvent(0, evJoin1, 0);   // gather needs CSR

    int gatherBlocks = (NN * 32 + 255) / 256;

    for (int i = 0; i < DEPTH; i++) {
        if (i > 0) {
            size_t wo = (size_t)i * HH * HH;
            gemm_dual64_kernel<<<dim3(TILES, 2), 128, SM_DUAL>>>(pxh, pBG + wo, pBL + wo, phG, phL, NN);
        }
        int res = (i > 0) ? 1 : 0;
        gather_ln_kernel<<<dim3(gatherBlocks, 2), 256>>>(
            (const uint2*)phG, (const uint2*)phL, (const float4*)px,
            prowG, prowL, pedgeG, pedgeL, pdinvG, pdinvL,
            (const float4*)(bG + (size_t)i * HH), (const float4*)(bL + (size_t)i * HH),
            (const float4*)ln_g, (const float4*)ln_b, pcat, res);
        const __half* Bl0 = pBlin + (size_t)i * HH * 2 * HH;
        const __half* Bl1 = Bl0 + (size_t)64 * 2 * HH;
        const float* lb = linb + (size_t)i * HH;
        float* xdst = (i == DEPTH - 1) ? (out + (size_t)NN * OUTC) : px;
        gemm_bres_kernel<64, 256><<<dim3(TILES, 2), 256, SM_CONCAT>>>(
            pcat, 2 * HH, Bl0, Bl1, xdst, xdst + 64, HH, pxh, pxh + 64, lb, lb + 64, NN);
    }

    gemm_bres_kernel<64, 128><<<dim3(TILES, 1), 256, SM_FINAL>>>(
        pxh, HH, pBfin, nullptr, out, nullptr, OUTC, nullptr, nullptr, finb, nullptr, NN);
}

// round 17
// speedup vs baseline: 1.1497x; 1.1497x over previous
#include <cuda_runtime.h>
#include <cuda_bf16.h>
#include <cuda_fp16.h>
#include <cuda_pipeline.h>
#include <mma.h>
#include <cstdint>

using namespace nvcuda;

#define NN 50000
#define HH 128
#define OUTC 64
#define DEPTH 3
#define LN_EPS 1e-5f
#define EGMAX 600000
#define ELMAX 400000
#define NB196 196
#define TILES 391          // ceil(NN/128)
#define LDT 40             // A smem leading dim (fp16): 80B rows, conflict-free LDSM
#define ATSZ (128 * LDT)   // 5120 elems per A tile

// ================= scratch =================
__device__ __half g_xh[NN * HH];
__device__ __half g_hG[NN * HH];
__device__ __half g_hL[NN * HH];
__device__ __half g_cat[NN * 2 * HH];
__device__ int   g_degG[NN];
__device__ int   g_degL[NN];
__device__ float g_dinvG[NN];
__device__ float g_dinvL[NN];
__device__ int   g_rowptrG[NN + 1];
__device__ int   g_rowptrL[NN + 1];
__device__ int   g_fillG[NN];
__device__ int   g_fillL[NN];
__device__ int2  g_edgeG[EGMAX];     // (col, coef bits)
__device__ int2  g_edgeL[ELMAX];
__device__ int   g_bsum[2][256];
// fp16 transposed weights [layer][N][K]
__device__ __half g_BG[DEPTH * HH * HH];
__device__ __half g_BL[DEPTH * HH * HH];
__device__ __half g_Blin[DEPTH * HH * 2 * HH];
__device__ __half g_Bfin[OUTC * HH];

// ================= setup kernels =================
__global__ void zero_deg_kernel(int* degG, int* degL, int n) {
    int i = blockIdx.x * blockDim.x + threadIdx.x;
    if (i < n) { degG[i] = 0; degL[i] = 0; }
}

__global__ void wsplit_all_kernel(const float* __restrict__ WG, const float* __restrict__ WLp,
                                  const float* __restrict__ linW, const float* __restrict__ finW,
                                  __half* BG, __half* BL, __half* Blin, __half* Bfin) {
    int seg = blockIdx.z;
    const float* W;
    __half* B;
    int K, N;
    if (seg < 3)      { K = HH;     N = HH;   W = WG  + (size_t)seg * HH * HH;           B = BG  + (size_t)seg * HH * HH; }
    else if (seg < 6) { K = HH;     N = HH;   W = WLp + (size_t)(seg - 3) * HH * HH;     B = BL  + (size_t)(seg - 3) * HH * HH; }
    else if (seg < 9) { K = 2 * HH; N = HH;   W = linW + (size_t)(seg - 6) * 2 * HH * HH; B = Blin + (size_t)(seg - 6) * 2 * HH * HH; }
    else              { K = HH;     N = OUTC; W = finW;                                   B = Bfin; }
    int n0 = blockIdx.x * 32, k0 = blockIdx.y * 32;
    if (n0 >= N || k0 >= K) return;
    __shared__ float t[32][33];
    int tx = threadIdx.x, ty = threadIdx.y;
    #pragma unroll
    for (int i = 0; i < 4; i++)
        t[ty + i * 8][tx] = W[(size_t)(k0 + ty + i * 8) * N + n0 + tx];
    __syncthreads();
    #pragma unroll
    for (int i = 0; i < 4; i++)
        B[(size_t)(n0 + ty + i * 8) * K + k0 + tx] = __float2half(t[tx][ty + i * 8]);
}

__global__ void init_split_kernel(const float4* __restrict__ xin4, __half* __restrict__ xh) {
    int i = blockIdx.x * blockDim.x + threadIdx.x;
    if (i >= NN * HH / 4) return;
    float4 v = xin4[i];
    __half2 a = __floats2half2_rn(v.x, v.y);
    __half2 b = __floats2half2_rn(v.z, v.w);
    uint2 u = { *(unsigned*)&a, *(unsigned*)&b };
    *reinterpret_cast<uint2*>(&xh[i * 4]) = u;
}

__global__ void count_deg_kernel(const int* __restrict__ dstG, int EG,
                                 const int* __restrict__ dstL, int EL,
                                 int* __restrict__ degG, int* __restrict__ degL) {
    int i = blockIdx.x * blockDim.x + threadIdx.x;
    if (i < EG) atomicAdd(&degG[dstG[i]], 1);
    else if (i < EG + EL) atomicAdd(&degL[dstL[i - EG]], 1);
}
__global__ void make_dinv_kernel(const int* __restrict__ degG, float* __restrict__ dinvG,
                                 const int* __restrict__ degL, float* __restrict__ dinvL, int n) {
    int i = blockIdx.x * blockDim.x + threadIdx.x;
    if (i < n) {
        dinvG[i] = rsqrtf((float)degG[i] + 2.0f);
        dinvL[i] = rsqrtf((float)degL[i] + 2.0f);
    }
}
__global__ void scan_block_kernel(const int* __restrict__ degG, const int* __restrict__ degL,
                                  int* __restrict__ rowG, int* __restrict__ rowL,
                                  int* __restrict__ bsum, int n) {
    __shared__ int s[256];
    const int* deg = blockIdx.y ? degL : degG;
    int* rowptr = blockIdx.y ? rowL : rowG;
    int* bs = bsum + blockIdx.y * 256;
    int i = blockIdx.x * 256 + threadIdx.x;
    int v = (i < n) ? deg[i] : 0;
    s[threadIdx.x] = v;
    __syncthreads();
    #pragma unroll
    for (int o = 1; o < 256; o <<= 1) {
        int t = (threadIdx.x >= o) ? s[threadIdx.x - o] : 0;
        __syncthreads();
        s[threadIdx.x] += t;
        __syncthreads();
    }
    if (i < n) rowptr[i] = s[threadIdx.x] - v;
    if (threadIdx.x == 255) bs[blockIdx.x] = s[255];
}
__global__ void scan_aux_kernel(int* bsum, int nb) {
    if (threadIdx.x == 0) {
        for (int y = 0; y < 2; y++) {
            int run = 0;
            int* b = bsum + y * 256;
            for (int i = 0; i < nb; i++) { int t = b[i]; b[i] = run; run += t; }
        }
    }
}
__global__ void scan_add_kernel(int* __restrict__ rowG, int* __restrict__ rowL,
                                int* __restrict__ fillG, int* __restrict__ fillL,
                                const int* __restrict__ bsum, int n, int EG, int EL) {
    int* rowptr = blockIdx.y ? rowL : rowG;
    int* fill = blockIdx.y ? fillL : fillG;
    const int* bs = bsum + blockIdx.y * 256;
    int E = blockIdx.y ? EL : EG;
    int i = blockIdx.x * 256 + threadIdx.x;
    if (i < n) {
        int v = rowptr[i] + bs[i >> 8];
        rowptr[i] = v;
        fill[i] = v;
    }
    if (i == 0) rowptr[n] = E;
}
__global__ void fill_csr_kernel(const int* __restrict__ Ge, int EG, const int* __restrict__ Le, int EL,
                                int* __restrict__ fillG, int* __restrict__ fillL,
                                int2* __restrict__ edgeG, int2* __restrict__ edgeL,
                                const float* __restrict__ dinvG, const float* __restrict__ dinvL) {
    int e = blockIdx.x * blockDim.x + threadIdx.x;
    const int* src; const int* dst; int* fill; int2* edge; const float* dinv; int E;
    if (blockIdx.y == 0) { src = Ge; dst = Ge + EG; fill = fillG; edge = edgeG; dinv = dinvG; E = EG; }
    else                 { src = Le; dst = Le + EL; fill = fillL; edge = edgeL; dinv = dinvL; E = EL; }
    if (e < E) {
        int s = src[e], d = dst[e];
        int p = atomicAdd(&fill[d], 1);
        float c = dinv[s] * dinv[d];
        edge[p] = make_int2(s, __float_as_int(c));
    }
}

// ===== dual-branch GEMM K=128 NOUT=128: 4 warps, 64x64 warp tiles, B resident, fp16 out ====
__global__ __launch_bounds__(128, 2)
void gemm_dual64_kernel(const __half* __restrict__ A,
                        const __half* __restrict__ B0, const __half* __restrict__ B1,
                        __half* __restrict__ Ch0, __half* __restrict__ Ch1, int M) {
    constexpr int K = 128;
    constexpr int LDB = 136;
    constexpr int BTILE = 128 * LDB;
    extern __shared__ __half sm[];
    __half* Bs = sm;
    __half* Astg = sm + BTILE;

    const __half* gB = blockIdx.y ? B1 : B0;
    __half* Ch = blockIdx.y ? Ch1 : Ch0;

    const int tid = threadIdx.x;
    const int wid = tid >> 5;
    const int lane = tid & 31;
    const int wr = wid >> 1;
    const int wc = wid & 1;
    const int row0 = blockIdx.x * 128;

    wmma::fragment<wmma::accumulator, 16, 16, 16, float> acc[4][4];
    #pragma unroll
    for (int i = 0; i < 4; i++)
        #pragma unroll
        for (int j = 0; j < 4; j++)
            wmma::fill_fragment(acc[i][j], 0.0f);

    auto load_A = [&](int s, int kc) {
        __half* base = Astg + s * ATSZ;
        #pragma unroll
        for (int c = tid; c < 512; c += 128) {
            int r = c >> 2;
            int ko = (c & 3) * 8;
            int gr = row0 + r;
            if (gr < M)
                __pipeline_memcpy_async(&base[r * LDT + ko], &A[(size_t)gr * K + kc * 32 + ko], 16);
        }
    };

    #pragma unroll
    for (int c = tid; c < 128 * 16; c += 128) {
        int r = c >> 4;
        int ko = (c & 15) * 8;
        __pipeline_memcpy_async(&Bs[r * LDB + ko], &gB[(size_t)r * K + ko], 16);
    }
    load_A(0, 0);
    __pipeline_commit();

    #pragma unroll
    for (int kc = 0; kc < 4; kc++) {
        if (kc + 1 < 4) {
            load_A((kc + 1) & 1, kc + 1);
            __pipeline_commit();
            __pipeline_wait_prior(1);
        } else {
            __pipeline_wait_prior(0);
        }
        __syncthreads();

        __half* Ahs = Astg + (kc & 1) * ATSZ;

        #pragma unroll
        for (int ks = 0; ks < 32; ks += 16) {
            int kcol = kc * 32 + ks;
            wmma::fragment<wmma::matrix_a, 16, 16, 16, __half, wmma::row_major> fa[4];
            #pragma unroll
            for (int i = 0; i < 4; i++)
                wmma::load_matrix_sync(fa[i], &Ahs[(wr * 64 + i * 16) * LDT + ks], LDT);
            wmma::fragment<wmma::matrix_b, 16, 16, 16, __half, wmma::col_major> fb[4];
            #pragma unroll
            for (int j = 0; j < 4; j++)
                wmma::load_matrix_sync(fb[j], &Bs[(wc * 64 + j * 16) * LDB + kcol], LDB);
            #pragma unroll
            for (int i = 0; i < 4; i++)
                #pragma unroll
                for (int j = 0; j < 4; j++)
                    wmma::mma_sync(acc[i][j], fa[i], fb[j], acc[i][j]);
        }
        __syncthreads();
    }

    float* st = reinterpret_cast<float*>(sm) + wid * 320;
    #pragma unroll
    for (int i = 0; i < 4; i++)
        #pragma unroll
        for (int j = 0; j < 4; j++) {
            wmma::store_matrix_sync(st, acc[i][j], 20, wmma::mem_row_major);
            __syncwarp();
            #pragma unroll
            for (int e = 0; e < 8; e++) {
                int idx = lane + e * 32;
                int r = idx >> 4;
                int c = idx & 15;
                int grow = row0 + wr * 64 + i * 16 + r;
                int gcol = wc * 64 + j * 16 + c;
                if (grow < M)
                    Ch[(size_t)grow * 128 + gcol] = __float2half(st[r * 20 + c]);
            }
            __syncwarp();
        }
}

// ================= fp16 GEMM, B resident, A double-buffered (8 warps, 32xHALFN tiles) =======
template <int NOUT, int KK>
__global__ __launch_bounds__(256, 2)
void gemm_bres_kernel(const __half* __restrict__ A, int lda,
                      const __half* __restrict__ B0, const __half* __restrict__ B1,
                      float* __restrict__ C0, float* __restrict__ C1, int ldc,
                      __half* __restrict__ Ch0, __half* __restrict__ Ch1,
                      const float* __restrict__ bias0, const float* __restrict__ bias1,
                      int M) {
    constexpr int HALFN = NOUT / 2;
    constexpr int NF = HALFN / 16;
    constexpr int LDB = KK + 8;
    constexpr int BTILE = NOUT * LDB;
    constexpr int NC = KK / 32;
    extern __shared__ __half sm[];
    __half* Bs = sm;
    __half* Astg = sm + BTILE;

    const __half* gB = blockIdx.y ? B1 : B0;
    float* C = blockIdx.y ? C1 : C0;
    __half* Ch = blockIdx.y ? Ch1 : Ch0;
    const float* bias = blockIdx.y ? bias1 : bias0;

    const int tid = threadIdx.x;
    const int wid = tid >> 5;
    const int lane = tid & 31;
    const int wr = wid >> 1;
    const int wc = wid & 1;
    const int row0 = blockIdx.x * 128;

    wmma::fragment<wmma::accumulator, 16, 16, 16, float> acc[2][NF];
    #pragma unroll
    for (int i = 0; i < 2; i++)
        #pragma unroll
        for (int j = 0; j < NF; j++)
            wmma::fill_fragment(acc[i][j], 0.0f);

    auto load_A = [&](int s, int kc) {
        __half* base = Astg + s * ATSZ;
        #pragma unroll
        for (int c = tid; c < 512; c += 256) {
            int r = c >> 2;
            int ko = (c & 3) * 8;
            int gr = row0 + r;
            if (gr < M)
                __pipeline_memcpy_async(&base[r * LDT + ko], &A[(size_t)gr * lda + kc * 32 + ko], 16);
        }
    };

    #pragma unroll
    for (int c = tid; c < NOUT * (KK / 8); c += 256) {
        int r = c / (KK / 8);
        int ko = (c % (KK / 8)) * 8;
        __pipeline_memcpy_async(&Bs[r * LDB + ko], &gB[(size_t)r * KK + ko], 16);
    }
    load_A(0, 0);
    __pipeline_commit();

    #pragma unroll
    for (int kc = 0; kc < NC; kc++) {
        if (kc + 1 < NC) {
            load_A((kc + 1) & 1, kc + 1);
            __pipeline_commit();
            __pipeline_wait_prior(1);
        } else {
            __pipeline_wait_prior(0);
        }
        __syncthreads();

        __half* Ahs = Astg + (kc & 1) * ATSZ;

        #pragma unroll
        for (int ks = 0; ks < 32; ks += 16) {
            int kcol = kc * 32 + ks;
            wmma::fragment<wmma::matrix_a, 16, 16, 16, __half, wmma::row_major> fa[2];
            #pragma unroll
            for (int i = 0; i < 2; i++)
                wmma::load_matrix_sync(fa[i], &Ahs[(wr * 32 + i * 16) * LDT + ks], LDT);
            wmma::fragment<wmma::matrix_b, 16, 16, 16, __half, wmma::col_major> fb[NF];
            #pragma unroll
            for (int j = 0; j < NF; j++)
                wmma::load_matrix_sync(fb[j], &Bs[(wc * HALFN + j * 16) * LDB + kcol], LDB);
            #pragma unroll
            for (int i = 0; i < 2; i++)
                #pragma unroll
                for (int j = 0; j < NF; j++)
                    wmma::mma_sync(acc[i][j], fa[i], fb[j], acc[i][j]);
        }
        __syncthreads();
    }

    float* st = reinterpret_cast<float*>(sm) + wid * 320;
    #pragma unroll
    for (int i = 0; i < 2; i++)
        #pragma unroll
        for (int j = 0; j < NF; j++) {
            wmma::store_matrix_sync(st, acc[i][j], 20, wmma::mem_row_major);
            __syncwarp();
            #pragma unroll
            for (int e = 0; e < 8; e++) {
                int idx = lane + e * 32;
                int r = idx >> 4;
                int c = idx & 15;
                int grow = row0 + wr * 32 + i * 16 + r;
                int gcol = wc * HALFN + j * 16 + c;
                if (grow < M) {
                    float v = st[r * 20 + c];
                    if (bias) v += __ldg(&bias[gcol]);
                    if (C)  C[(size_t)grow * ldc + gcol] = v;
                    if (Ch) Ch[(size_t)grow * ldc + gcol] = __float2half(v);
                }
            }
            __syncwarp();
        }
}

// ===== fused gather (R15 form) + LN + ReLU + fp16 residual + concat ======
__global__ void gather_ln_kernel(const uint2* __restrict__ hG8, const uint2* __restrict__ hL8,
                                 const uint2* __restrict__ xh8,
                                 const int* __restrict__ rowG, const int* __restrict__ rowL,
                                 const int2* __restrict__ edgeG, const int2* __restrict__ edgeL,
                                 const float* __restrict__ dinvG, const float* __restrict__ dinvL,
                                 const float4* __restrict__ biasG4, const float4* __restrict__ biasL4,
                                 const float4* __restrict__ g4, const float4* __restrict__ b4,
                                 __half* __restrict__ cat, int residual) {
    int warp = (blockIdx.x * blockDim.x + threadIdx.x) >> 5;
    int lane = threadIdx.x & 31;
    if (warp >= NN) return;
    int n = warp;
    int half = blockIdx.y;

    const uint2* h8 = half ? hL8 : hG8;
    const int* rowptr = half ? rowL : rowG;
    const int2* edge = half ? edgeL : edgeG;
    const float* dinv = half ? dinvL : dinvG;
    const float4* bias4 = half ? biasL4 : biasG4;

    auto h2f4 = [](uint2 u) -> float4 {
        __half2 a = *reinterpret_cast<__half2*>(&u.x);
        __half2 b = *reinterpret_cast<__half2*>(&u.y);
        float2 fa = __half22float2(a);
        float2 fb = __half22float2(b);
        return make_float4(fa.x, fa.y, fb.x, fb.y);
    };

    float dv = __ldg(&dinv[n]);
    float sl = 2.0f * dv * dv;
    float4 h = h2f4(h8[n * 32 + lane]);
    float4 bb = __ldg(&bias4[lane]);
    float4 acc;
    acc.x = h.x * sl + bb.x;
    acc.y = h.y * sl + bb.y;
    acc.z = h.z * sl + bb.z;
    acc.w = h.w * sl + bb.w;

    int e = __ldg(&rowptr[n]);
    int e1 = __ldg(&rowptr[n + 1]);

    for (; e + 7 < e1; e += 8) {
        int2 p[8];
        #pragma unroll
        for (int q = 0; q < 8; q++) p[q] = __ldg(&edge[e + q]);
        uint2 u[8];
        #pragma unroll
        for (int q = 0; q < 8; q++) u[q] = h8[p[q].x * 32 + lane];
        #pragma unroll
        for (int q = 0; q < 8; q++) {
            float c = __int_as_float(p[q].y);
            float4 v = h2f4(u[q]);
            acc.x += c * v.x;
            acc.y += c * v.y;
            acc.z += c * v.z;
            acc.w += c * v.w;
        }
    }
    if (e + 3 < e1) {
        int2 p[4];
        #pragma unroll
        for (int q = 0; q < 4; q++) p[q] = __ldg(&edge[e + q]);
        uint2 u[4];
        #pragma unroll
        for (int q = 0; q < 4; q++) u[q] = h8[p[q].x * 32 + lane];
        #pragma unroll
        for (int q = 0; q < 4; q++) {
            float c = __int_as_float(p[q].y);
            float4 v = h2f4(u[q]);
            acc.x += c * v.x;
            acc.y += c * v.y;
            acc.z += c * v.z;
            acc.w += c * v.w;
        }
        e += 4;
    }
    for (; e < e1; e++) {
        int2 p0 = __ldg(&edge[e]);
        float c0 = __int_as_float(p0.y);
        float4 v0 = h2f4(h8[p0.x * 32 + lane]);
        acc.x += c0 * v0.x; acc.y += c0 * v0.y; acc.z += c0 * v0.z; acc.w += c0 * v0.w;
    }

    float s1 = acc.x + acc.y + acc.z + acc.w;
    float s2 = acc.x * acc.x + acc.y * acc.y + acc.z * acc.z + acc.w * acc.w;
    #pragma unroll
    for (int o = 16; o > 0; o >>= 1) {
        s1 += __shfl_xor_sync(0xffffffffu, s1, o);
        s2 += __shfl_xor_sync(0xffffffffu, s2, o);
    }
    float mu = s1 * (1.0f / HH);
    float var = s2 * (1.0f / HH) - mu * mu;
    float rstd = rsqrtf(var + LN_EPS);

    float4 gg = __ldg(&g4[lane]);
    float4 be = __ldg(&b4[lane]);
    float4 y;
    y.x = fmaxf((acc.x - mu) * rstd * gg.x + be.x, 0.0f);
    y.y = fmaxf((acc.y - mu) * rstd * gg.y + be.y, 0.0f);
    y.z = fmaxf((acc.z - mu) * rstd * gg.z + be.z, 0.0f);
    y.w = fmaxf((acc.w - mu) * rstd * gg.w + be.w, 0.0f);
    if (residual) {
        float4 xv = h2f4(xh8[n * 32 + lane]);
        y.x += xv.x; y.y += xv.y; y.z += xv.z; y.w += xv.w;
    }
    __half2 ya = __floats2half2_rn(y.x, y.y);
    __half2 yb = __floats2half2_rn(y.z, y.w);
    uint2 u = { *(unsigned*)&ya, *(unsigned*)&yb };
    *reinterpret_cast<uint2*>(&cat[(size_t)n * 256 + half * 128 + lane * 4]) = u;
}

// ================= launch =================
extern "C" void kernel_launch(void* const* d_in, const int* in_sizes, int n_in,
                              void* d_out, int out_size) {
    const float* x_in  = (const float*)d_in[0];
    const float* WL    = (const float*)d_in[1];
    const float* bL    = (const float*)d_in[2];
    const float* WG    = (const float*)d_in[3];
    const float* bG    = (const float*)d_in[4];
    const float* linW  = (const float*)d_in[5];
    const float* linb  = (const float*)d_in[6];
    const float* ln_g  = (const float*)d_in[7];
    const float* ln_b  = (const float*)d_in[8];
    const float* finW  = (const float*)d_in[9];
    const float* finb  = (const float*)d_in[10];
    const int*   Ge    = (const int*)d_in[11];
    const int*   Le    = (const int*)d_in[12];
    int E_G = in_sizes[11] / 2;
    int E_L = in_sizes[12] / 2;
    float* out = (float*)d_out;

    float *pdinvG, *pdinvL;
    __half *pxh, *phG, *phL, *pcat;
    int *pdegG, *pdegL, *prowG, *prowL, *pfillG, *pfillL, *pbsum;
    int2 *pedgeG, *pedgeL;
    __half *pBG, *pBL, *pBlin, *pBfin;
    cudaGetSymbolAddress((void**)&pxh,    g_xh);
    cudaGetSymbolAddress((void**)&phG,    g_hG);
    cudaGetSymbolAddress((void**)&phL,    g_hL);
    cudaGetSymbolAddress((void**)&pcat,   g_cat);
    cudaGetSymbolAddress((void**)&pdegG,  g_degG);
    cudaGetSymbolAddress((void**)&pdegL,  g_degL);
    cudaGetSymbolAddress((void**)&pdinvG, g_dinvG);
    cudaGetSymbolAddress((void**)&pdinvL, g_dinvL);
    cudaGetSymbolAddress((void**)&prowG,  g_rowptrG);
    cudaGetSymbolAddress((void**)&prowL,  g_rowptrL);
    cudaGetSymbolAddress((void**)&pfillG, g_fillG);
    cudaGetSymbolAddress((void**)&pfillL, g_fillL);
    cudaGetSymbolAddress((void**)&pedgeG, g_edgeG);
    cudaGetSymbolAddress((void**)&pedgeL, g_edgeL);
    cudaGetSymbolAddress((void**)&pbsum,  g_bsum);
    cudaGetSymbolAddress((void**)&pBG,    g_BG);
    cudaGetSymbolAddress((void**)&pBL,    g_BL);
    cudaGetSymbolAddress((void**)&pBlin,  g_Blin);
    cudaGetSymbolAddress((void**)&pBfin,  g_Bfin);

    const int SM_DUAL   = (128 * 136 + 2 * ATSZ) * 2;    // 55296
    const int SM_CONCAT = (64 * 264 + 2 * ATSZ) * 2;     // 54272
    const int SM_FINAL  = (64 * 136 + 2 * ATSZ) * 2;     // 37888

    static cudaStream_t s1 = nullptr;
    static cudaEvent_t evFork1, evJoin1;
    static int attr_set = 0;
    if (!attr_set) {
        cudaFuncSetAttribute((const void*)gemm_dual64_kernel, cudaFuncAttributeMaxDynamicSharedMemorySize, SM_DUAL);
        cudaFuncSetAttribute((const void*)gemm_bres_kernel<64, 256>, cudaFuncAttributeMaxDynamicSharedMemorySize, SM_CONCAT);
        cudaFuncSetAttribute((const void*)gemm_bres_kernel<64, 128>, cudaFuncAttributeMaxDynamicSharedMemorySize, SM_FINAL);
        cudaStreamCreateWithFlags(&s1, cudaStreamNonBlocking);
        cudaEventCreateWithFlags(&evFork1, cudaEventDisableTiming);
        cudaEventCreateWithFlags(&evJoin1, cudaEventDisableTiming);
        attr_set = 1;
    }

    // ---- fork: CSR build on side stream ----
    cudaEventRecord(evFork1, 0);
    cudaStreamWaitEvent(s1, evFork1, 0);

    zero_deg_kernel<<<NB196, 256, 0, s1>>>(pdegG, pdegL, NN);
    count_deg_kernel<<<(E_G + E_L + 255) / 256, 256, 0, s1>>>(Ge + E_G, E_G, Le + E_L, E_L, pdegG, pdegL);
    make_dinv_kernel<<<NB196, 256, 0, s1>>>(pdegG, pdinvG, pdegL, pdinvL, NN);
    scan_block_kernel<<<dim3(NB196, 2), 256, 0, s1>>>(pdegG, pdegL, prowG, prowL, pbsum, NN);
    scan_aux_kernel<<<1, 32, 0, s1>>>(pbsum, NB196);
    scan_add_kernel<<<dim3(NB196, 2), 256, 0, s1>>>(prowG, prowL, pfillG, pfillL, pbsum, NN, E_G, E_L);
    int fe = (E_G > E_L ? E_G : E_L);
    fill_csr_kernel<<<dim3((fe + 255) / 256, 2), 256, 0, s1>>>(Ge, E_G, Le, E_L,
        pfillG, pfillL, pedgeG, pedgeL, pdinvG, pdinvL);
    cudaEventRecord(evJoin1, s1);

    wsplit_all_kernel<<<dim3(4, 8, 10), dim3(32, 8)>>>(WG, WL, linW, finW, pBG, pBL, pBlin, pBfin);
    init_split_kernel<<<(NN * HH / 4 + 255) / 256, 256>>>((const float4*)x_in, pxh);
    gemm_dual64_kernel<<<dim3(TILES, 2), 128, SM_DUAL>>>(pxh, pBG, pBL, phG, phL, NN);

    cudaStreamWaitEvent(0, evJoin1, 0);   // gather needs CSR

    int gatherBlocks = (NN * 32 + 255) / 256;

    for (int i = 0; i < DEPTH; i++) {
        if (i > 0) {
            size_t wo = (size_t)i * HH * HH;
            gemm_dual64_kernel<<<dim3(TILES, 2), 128, SM_DUAL>>>(pxh, pBG + wo, pBL + wo, phG, phL, NN);
        }
        int res = (i > 0) ? 1 : 0;
        gather_ln_kernel<<<dim3(gatherBlocks, 2), 256>>>(
            (const uint2*)phG, (const uint2*)phL, (const uint2*)pxh,
            prowG, prowL, pedgeG, pedgeL, pdinvG, pdinvL,
            (const float4*)(bG + (size_t)i * HH), (const float4*)(bL + (size_t)i * HH),
            (const float4*)ln_g, (const float4*)ln_b, pcat, res);
        const __half* Bl0 = pBlin + (size_t)i * HH * 2 * HH;
        const __half* Bl1 = Bl0 + (size_t)64 * 2 * HH;
        const float* lb = linb + (size_t)i * HH;
        // fp32 x only needed on the last layer (written straight into the out2 region)
        float* xdst = (i == DEPTH - 1) ? (out + (size_t)NN * OUTC) : nullptr;
        gemm_bres_kernel<64, 256><<<dim3(TILES, 2), 256, SM_CONCAT>>>(
            pcat, 2 * HH, Bl0, Bl1, xdst, xdst ? xdst + 64 : nullptr, HH,
            pxh, pxh + 64, lb, lb + 64, NN);
    }

    gemm_bres_kernel<64, 128><<<dim3(TILES, 1), 256, SM_FINAL>>>(
        pxh, HH, pBfin, nullptr, out, nullptr, OUTC, nullptr, nullptr, finb, nullptr, NN);
}